// round 2
// baseline (speedup 1.0000x reference)
#include <cuda_runtime.h>
#include <cuda_bf16.h>

#define NN 100000
#define NE 1600000
#define NG 512

// ---------------- scratch (device globals, float4 => 16B-aligned) --------
__device__ int    g_deg[NN];
__device__ float  g_dis[NN];
__device__ float4 g_u4[NN];            // 4-dim dis-scaled features
__device__ float4 g_acc4[NN];          // 4-dim edge accumulator
__device__ float4 g_h[NN * 32];        // node features (post-ReLU), 128 f32/node
__device__ float4 g_u[NN * 32];        // dis-scaled projected features
__device__ float4 g_acc[NN * 32];      // edge-scatter accumulator
__device__ float4 g_pool[NG * 32];
__device__ int    g_cnt[NG];

// ---------------- init: deg=1 (self loop), zero small accumulators -------
__global__ void k_init(int n) {
    int i = blockIdx.x * blockDim.x + threadIdx.x;
    if (i < n) {
        g_deg[i] = 1;
        g_acc4[i] = make_float4(0.f, 0.f, 0.f, 0.f);
    }
    if (i < NG * 32) g_pool[i] = make_float4(0.f, 0.f, 0.f, 0.f);
    if (i < NG)      g_cnt[i] = 0;
}

// ---------------- degree count over dst ---------------------------------
__global__ void k_deg(const int* __restrict__ dst, int E) {
    int e = blockIdx.x * blockDim.x + threadIdx.x;
    if (e >= E) return;
    atomicAdd(&g_deg[dst[e]], 1);
}

__global__ void k_dis(int n) {
    int i = blockIdx.x * blockDim.x + threadIdx.x;
    if (i >= n) return;
    g_dis[i] = rsqrtf((float)g_deg[i]);
}

// ---------------- dense1: h0 = relu(x@W_d1+b), u4 = dis * h0 ------------
__global__ void k_dense1(const float* __restrict__ x,
                         const float* __restrict__ W,
                         const float* __restrict__ b, int n) {
    int i = blockIdx.x * blockDim.x + threadIdx.x;
    if (i >= n) return;
    float4 xi = ((const float4*)x)[i];
    float d = g_dis[i];
    float4 o;
    o.x = fmaxf(b[0] + xi.x * W[0] + xi.y * W[4] + xi.z * W[8]  + xi.w * W[12], 0.f) * d;
    o.y = fmaxf(b[1] + xi.x * W[1] + xi.y * W[5] + xi.z * W[9]  + xi.w * W[13], 0.f) * d;
    o.z = fmaxf(b[2] + xi.x * W[2] + xi.y * W[6] + xi.z * W[10] + xi.w * W[14], 0.f) * d;
    o.w = fmaxf(b[3] + xi.x * W[3] + xi.y * W[7] + xi.z * W[11] + xi.w * W[15], 0.f) * d;
    g_u4[i] = o;
}

// ---------------- edge scatter, 4-dim features --------------------------
__global__ void k_edge4(const int* __restrict__ src,
                        const int* __restrict__ dst, int E) {
    int e = blockIdx.x * blockDim.x + threadIdx.x;
    if (e >= E) return;
    float4 v = g_u4[src[e]];
    float4* p = &g_acc4[dst[e]];
    asm volatile("red.global.add.v4.f32 [%0], {%1,%2,%3,%4};"
                 :: "l"(p), "f"(v.x), "f"(v.y), "f"(v.z), "f"(v.w) : "memory");
}

// ---------------- layer1 output: h1 = relu((dis*(acc4+u4)) @ W_g1 + b) --
__global__ void k_layer1(const float* __restrict__ Wg1,
                         const float* __restrict__ bg1, int n) {
    int gid = blockIdx.x * blockDim.x + threadIdx.x;
    int i = gid >> 5;
    int lane = gid & 31;
    if (i >= n) return;
    float4 a = g_acc4[i];
    float4 u = g_u4[i];
    float d = g_dis[i];
    float a0 = d * (a.x + u.x), a1 = d * (a.y + u.y);
    float a2 = d * (a.z + u.z), a3 = d * (a.w + u.w);
    int c = lane * 4;
    float4 w0 = *(const float4*)(Wg1 + 0 * 128 + c);
    float4 w1 = *(const float4*)(Wg1 + 1 * 128 + c);
    float4 w2 = *(const float4*)(Wg1 + 2 * 128 + c);
    float4 w3 = *(const float4*)(Wg1 + 3 * 128 + c);
    float4 bb = *(const float4*)(bg1 + c);
    float4 o;
    o.x = fmaxf(bb.x + a0 * w0.x + a1 * w1.x + a2 * w2.x + a3 * w3.x, 0.f);
    o.y = fmaxf(bb.y + a0 * w0.y + a1 * w1.y + a2 * w2.y + a3 * w3.y, 0.f);
    o.z = fmaxf(bb.z + a0 * w0.z + a1 * w1.z + a2 * w2.z + a3 * w3.z, 0.f);
    o.w = fmaxf(bb.w + a0 * w0.w + a1 * w1.w + a2 * w2.w + a3 * w3.w, 0.f);
    g_h[(size_t)i * 32 + lane] = o;
}

// ---------------- zero big accumulator ----------------------------------
__global__ void k_zero_acc() {
    int i = blockIdx.x * blockDim.x + threadIdx.x;
    if (i < NN * 32) g_acc[i] = make_float4(0.f, 0.f, 0.f, 0.f);
}

// ---------------- SGEMM: U = dis[row] * (g_h @ W),  [n,128]x[128,128] ---
__global__ void __launch_bounds__(256, 2)
k_gemm_scale(const float* __restrict__ W, int n) {
    __shared__ float As[8][128];
    __shared__ float Bs[8][128];
    const int row0 = blockIdx.x * 128;
    const int t = threadIdx.x;
    const int tx = t & 15;   // col group 0..15
    const int ty = t >> 4;   // row group 0..15
    float acc[8][8];
#pragma unroll
    for (int i = 0; i < 8; i++)
#pragma unroll
        for (int j = 0; j < 8; j++) acc[i][j] = 0.f;

    const int lm = t >> 1;          // A-load row 0..127
    const int lk = (t & 1) * 4;     // A-load k offset 0/4
    const int bk = t >> 5;          // B-load k 0..7
    const int bn = (t & 31) * 4;    // B-load col

    const float* A = (const float*)g_h;
    for (int k0 = 0; k0 < 128; k0 += 8) {
        float4 av = make_float4(0.f, 0.f, 0.f, 0.f);
        int gr = row0 + lm;
        if (gr < n) av = *(const float4*)(A + (size_t)gr * 128 + k0 + lk);
        As[lk + 0][lm] = av.x;
        As[lk + 1][lm] = av.y;
        As[lk + 2][lm] = av.z;
        As[lk + 3][lm] = av.w;
        *(float4*)&Bs[bk][bn] = *(const float4*)(W + (size_t)(k0 + bk) * 128 + bn);
        __syncthreads();
#pragma unroll
        for (int k = 0; k < 8; k++) {
            float a[8], b[8];
            *(float4*)(a)     = *(const float4*)&As[k][ty * 4];
            *(float4*)(a + 4) = *(const float4*)&As[k][64 + ty * 4];
            *(float4*)(b)     = *(const float4*)&Bs[k][tx * 4];
            *(float4*)(b + 4) = *(const float4*)&Bs[k][64 + tx * 4];
#pragma unroll
            for (int i = 0; i < 8; i++)
#pragma unroll
                for (int j = 0; j < 8; j++) acc[i][j] += a[i] * b[j];
        }
        __syncthreads();
    }
    float* U = (float*)g_u;
#pragma unroll
    for (int i = 0; i < 8; i++) {
        int r = (i < 4) ? (row0 + ty * 4 + i) : (row0 + 64 + ty * 4 + (i - 4));
        if (r < n) {
            float d = g_dis[r];
            float4 v0 = make_float4(acc[i][0] * d, acc[i][1] * d, acc[i][2] * d, acc[i][3] * d);
            float4 v1 = make_float4(acc[i][4] * d, acc[i][5] * d, acc[i][6] * d, acc[i][7] * d);
            *(float4*)(U + (size_t)r * 128 + tx * 4) = v0;
            *(float4*)(U + (size_t)r * 128 + 64 + tx * 4) = v1;
        }
    }
}

// ---------------- edge scatter, 128-dim: warp per edge ------------------
__global__ void k_edge128(const int* __restrict__ src,
                          const int* __restrict__ dst, int E) {
    int w = (blockIdx.x * blockDim.x + threadIdx.x) >> 5;
    int lane = threadIdx.x & 31;
    if (w >= E) return;
    int s = src[w];
    int d = dst[w];
    float4 v = g_u[(size_t)s * 32 + lane];
    float4* p = &g_acc[(size_t)d * 32 + lane];
    asm volatile("red.global.add.v4.f32 [%0], {%1,%2,%3,%4};"
                 :: "l"(p), "f"(v.x), "f"(v.y), "f"(v.z), "f"(v.w) : "memory");
}

// ---------------- finalize: h = relu(dis*(acc+u) + b) -------------------
__global__ void k_fin(const float* __restrict__ bias, int n) {
    int idx = blockIdx.x * blockDim.x + threadIdx.x;
    if (idx >= n * 32) return;
    int i = idx >> 5;
    int c = idx & 31;
    float d = g_dis[i];
    float4 a = g_acc[(size_t)i * 32 + c];
    float4 u = g_u[(size_t)i * 32 + c];
    float4 b = *(const float4*)(bias + c * 4);
    float4 o;
    o.x = fmaxf(d * (a.x + u.x) + b.x, 0.f);
    o.y = fmaxf(d * (a.y + u.y) + b.y, 0.f);
    o.z = fmaxf(d * (a.z + u.z) + b.z, 0.f);
    o.w = fmaxf(d * (a.w + u.w) + b.w, 0.f);
    g_h[(size_t)i * 32 + c] = o;
}

// ---------------- pooling ------------------------------------------------
__global__ void k_pool_cnt(const int* __restrict__ batch, int n) {
    int i = blockIdx.x * blockDim.x + threadIdx.x;
    if (i >= n) return;
    atomicAdd(&g_cnt[batch[i]], 1);
}

__global__ void k_pool_sum(const int* __restrict__ batch, int n) {
    int idx = blockIdx.x * blockDim.x + threadIdx.x;
    int i = idx >> 5;
    int lane = idx & 31;
    if (i >= n) return;
    int b = batch[i];
    float4 v = g_h[(size_t)i * 32 + lane];
    float4* p = &g_pool[(size_t)b * 32 + lane];
    asm volatile("red.global.add.v4.f32 [%0], {%1,%2,%3,%4};"
                 :: "l"(p), "f"(v.x), "f"(v.y), "f"(v.z), "f"(v.w) : "memory");
}

// ---------------- final dense: out = (pool/cnt) @ W_d2 + b_d2 -----------
__global__ void k_out(const float* __restrict__ W,
                      const float* __restrict__ b,
                      float* __restrict__ out) {
    __shared__ float s[128];
    int g = blockIdx.x;
    int j = threadIdx.x;
    float inv = 1.f / fmaxf((float)g_cnt[g], 1.f);
    ((float*)&s[0])[j] = ((const float*)g_pool)[g * 128 + j] * inv;
    __syncthreads();
    float acc = b[j];
#pragma unroll 8
    for (int k = 0; k < 128; k++) acc += s[k] * W[k * 128 + j];
    out[g * 128 + j] = acc;
}

// ---------------- launch -------------------------------------------------
extern "C" void kernel_launch(void* const* d_in, const int* in_sizes, int n_in,
                              void* d_out, int out_size) {
    const float* x     = (const float*)d_in[0];
    const int*   ei    = (const int*)d_in[1];    // int32 (JAX x64 disabled)
    const int*   batch = (const int*)d_in[2];
    const float* W_d1 = (const float*)d_in[3];
    const float* b_d1 = (const float*)d_in[4];
    const float* W_g1 = (const float*)d_in[5];
    const float* b_g1 = (const float*)d_in[6];
    const float* W_g2 = (const float*)d_in[7];
    const float* b_g2 = (const float*)d_in[8];
    const float* W_g3 = (const float*)d_in[9];
    const float* b_g3 = (const float*)d_in[10];
    const float* W_d2 = (const float*)d_in[11];
    const float* b_d2 = (const float*)d_in[12];
    float* out = (float*)d_out;

    const int N = in_sizes[0] / 4;   // 100000
    const int E = in_sizes[1] / 2;   // 1600000
    const int* src = ei;
    const int* dst = ei + E;
    const int T = 256;

    // structure / normalization
    k_init<<<(N + T - 1) / T, T>>>(N);
    k_deg<<<(E + T - 1) / T, T>>>(dst, E);
    k_dis<<<(N + T - 1) / T, T>>>(N);

    // layer 1: aggregate 4-dim first, then project 4->128
    k_dense1<<<(N + T - 1) / T, T>>>(x, W_d1, b_d1, N);
    k_edge4<<<(E + T - 1) / T, T>>>(src, dst, E);
    k_layer1<<<(N * 32 + T - 1) / T, T>>>(W_g1, b_g1, N);

    const int gemm_blocks = (N + 127) / 128;
    const int edge_blocks = (int)(((long long)E * 32 + T - 1) / T);
    const int fin_blocks  = (N * 32 + T - 1) / T;
    const int zero_blocks = (NN * 32 + T - 1) / T;

    // layer 2
    k_gemm_scale<<<gemm_blocks, T>>>(W_g2, N);
    k_zero_acc<<<zero_blocks, T>>>();
    k_edge128<<<edge_blocks, T>>>(src, dst, E);
    k_fin<<<fin_blocks, T>>>(b_g2, N);

    // layer 3
    k_gemm_scale<<<gemm_blocks, T>>>(W_g3, N);
    k_zero_acc<<<zero_blocks, T>>>();
    k_edge128<<<edge_blocks, T>>>(src, dst, E);
    k_fin<<<fin_blocks, T>>>(b_g3, N);

    // pooling + head
    k_pool_cnt<<<(N + T - 1) / T, T>>>(batch, N);
    k_pool_sum<<<(N * 32 + T - 1) / T, T>>>(batch, N);
    k_out<<<NG, 128>>>(W_d2, b_d2, out);
}

// round 3
// speedup vs baseline: 1.7830x; 1.7830x over previous
#include <cuda_runtime.h>
#include <cuda_bf16.h>

#define NN 100000
#define NE 1600000
#define NG 512
#define NB_SCAN 391   // ceil(NN/256)

// ---------------- scratch (device globals, float4 => 16B-aligned) --------
__device__ int    g_deg[NN];         // degree incl. self-loop
__device__ float  g_dis[NN];         // 1/sqrt(deg)
__device__ float4 g_u4[NN];          // 4-dim dis-scaled features
__device__ float4 g_h[NN * 32];      // node features (post-ReLU), 128 f32/node
__device__ float4 g_u[NN * 32];      // dis-scaled projected features
__device__ int    g_rowstart[NN];    // CSR row offsets (by dst)
__device__ int    g_fillpos[NN];     // fill cursors
__device__ int    g_col[NE];         // CSR column (src) indices
__device__ int    g_bsum[512];       // scan block sums

// ---------------- init ---------------------------------------------------
__global__ void k_init(int n) {
    int i = blockIdx.x * blockDim.x + threadIdx.x;
    if (i < n) g_deg[i] = 1;
}

// ---------------- degree count over dst ----------------------------------
__global__ void k_deg(const int* __restrict__ dst, int E) {
    int e = blockIdx.x * blockDim.x + threadIdx.x;
    if (e >= E) return;
    atomicAdd(&g_deg[dst[e]], 1);
}

__global__ void k_dis(int n) {
    int i = blockIdx.x * blockDim.x + threadIdx.x;
    if (i >= n) return;
    g_dis[i] = rsqrtf((float)g_deg[i]);
}

// ---------------- CSR build: exclusive scan of (deg-1) -------------------
__global__ void k_scan1(int n) {
    __shared__ int s[256];
    int t = threadIdx.x;
    int i = blockIdx.x * 256 + t;
    int v = (i < n) ? (g_deg[i] - 1) : 0;
    s[t] = v;
    __syncthreads();
#pragma unroll
    for (int off = 1; off < 256; off <<= 1) {
        int x = (t >= off) ? s[t - off] : 0;
        __syncthreads();
        s[t] += x;
        __syncthreads();
    }
    if (i < n) g_rowstart[i] = s[t] - v;   // exclusive, block-local
    if (t == 255) g_bsum[blockIdx.x] = s[255];
}

__global__ void k_scan2(int nb) {
    __shared__ int s[512];
    int t = threadIdx.x;
    int v = (t < nb) ? g_bsum[t] : 0;
    s[t] = v;
    __syncthreads();
#pragma unroll
    for (int off = 1; off < 512; off <<= 1) {
        int x = (t >= off) ? s[t - off] : 0;
        __syncthreads();
        s[t] += x;
        __syncthreads();
    }
    if (t < nb) g_bsum[t] = s[t] - v;      // exclusive
}

__global__ void k_scan3(int n) {
    int i = blockIdx.x * 256 + threadIdx.x;
    if (i >= n) return;
    int r = g_rowstart[i] + g_bsum[blockIdx.x];
    g_rowstart[i] = r;
    g_fillpos[i]  = r;
}

__global__ void k_fill(const int* __restrict__ src,
                       const int* __restrict__ dst, int E) {
    int e = blockIdx.x * blockDim.x + threadIdx.x;
    if (e >= E) return;
    int pos = atomicAdd(&g_fillpos[dst[e]], 1);
    g_col[pos] = src[e];
}

// ---------------- dense1: u4 = dis * relu(x@W_d1+b) ----------------------
__global__ void k_dense1(const float* __restrict__ x,
                         const float* __restrict__ W,
                         const float* __restrict__ b, int n) {
    int i = blockIdx.x * blockDim.x + threadIdx.x;
    if (i >= n) return;
    float4 xi = ((const float4*)x)[i];
    float d = g_dis[i];
    float4 o;
    o.x = fmaxf(b[0] + xi.x * W[0] + xi.y * W[4] + xi.z * W[8]  + xi.w * W[12], 0.f) * d;
    o.y = fmaxf(b[1] + xi.x * W[1] + xi.y * W[5] + xi.z * W[9]  + xi.w * W[13], 0.f) * d;
    o.z = fmaxf(b[2] + xi.x * W[2] + xi.y * W[6] + xi.z * W[10] + xi.w * W[14], 0.f) * d;
    o.w = fmaxf(b[3] + xi.x * W[3] + xi.y * W[7] + xi.z * W[11] + xi.w * W[15], 0.f) * d;
    g_u4[i] = o;
}

// ---------------- fused layer1: agg(4-dim) + dense 4->128 + relu ---------
// warp per node: lanes split edges, shfl-reduce, then each lane does 4 cols
__global__ void k_layer1(const float* __restrict__ Wg1,
                         const float* __restrict__ bg1, int n) {
    int gid = blockIdx.x * blockDim.x + threadIdx.x;
    int i = gid >> 5;
    int lane = gid & 31;
    if (i >= n) return;
    int start = g_rowstart[i];
    int cnt   = g_deg[i] - 1;
    float4 a = make_float4(0.f, 0.f, 0.f, 0.f);
    for (int j = lane; j < cnt; j += 32) {
        float4 v = g_u4[g_col[start + j]];
        a.x += v.x; a.y += v.y; a.z += v.z; a.w += v.w;
    }
#pragma unroll
    for (int off = 16; off > 0; off >>= 1) {
        a.x += __shfl_xor_sync(0xffffffffu, a.x, off);
        a.y += __shfl_xor_sync(0xffffffffu, a.y, off);
        a.z += __shfl_xor_sync(0xffffffffu, a.z, off);
        a.w += __shfl_xor_sync(0xffffffffu, a.w, off);
    }
    float4 u = g_u4[i];
    float d = g_dis[i];
    float a0 = d * (a.x + u.x), a1 = d * (a.y + u.y);
    float a2 = d * (a.z + u.z), a3 = d * (a.w + u.w);
    int c = lane * 4;
    float4 w0 = *(const float4*)(Wg1 + 0 * 128 + c);
    float4 w1 = *(const float4*)(Wg1 + 1 * 128 + c);
    float4 w2 = *(const float4*)(Wg1 + 2 * 128 + c);
    float4 w3 = *(const float4*)(Wg1 + 3 * 128 + c);
    float4 bb = *(const float4*)(bg1 + c);
    float4 o;
    o.x = fmaxf(bb.x + a0 * w0.x + a1 * w1.x + a2 * w2.x + a3 * w3.x, 0.f);
    o.y = fmaxf(bb.y + a0 * w0.y + a1 * w1.y + a2 * w2.y + a3 * w3.y, 0.f);
    o.z = fmaxf(bb.z + a0 * w0.z + a1 * w1.z + a2 * w2.z + a3 * w3.z, 0.f);
    o.w = fmaxf(bb.w + a0 * w0.w + a1 * w1.w + a2 * w2.w + a3 * w3.w, 0.f);
    g_h[(size_t)i * 32 + lane] = o;
}

// ---------------- SGEMM: U = dis[row] * (g_h @ W),  [n,128]x[128,128] ---
__global__ void __launch_bounds__(256, 2)
k_gemm_scale(const float* __restrict__ W, int n) {
    __shared__ float As[8][128];
    __shared__ float Bs[8][128];
    const int row0 = blockIdx.x * 128;
    const int t = threadIdx.x;
    const int tx = t & 15;
    const int ty = t >> 4;
    float acc[8][8];
#pragma unroll
    for (int i = 0; i < 8; i++)
#pragma unroll
        for (int j = 0; j < 8; j++) acc[i][j] = 0.f;

    const int lm = t >> 1;
    const int lk = (t & 1) * 4;
    const int bk = t >> 5;
    const int bn = (t & 31) * 4;

    const float* A = (const float*)g_h;
    for (int k0 = 0; k0 < 128; k0 += 8) {
        float4 av = make_float4(0.f, 0.f, 0.f, 0.f);
        int gr = row0 + lm;
        if (gr < n) av = *(const float4*)(A + (size_t)gr * 128 + k0 + lk);
        As[lk + 0][lm] = av.x;
        As[lk + 1][lm] = av.y;
        As[lk + 2][lm] = av.z;
        As[lk + 3][lm] = av.w;
        *(float4*)&Bs[bk][bn] = *(const float4*)(W + (size_t)(k0 + bk) * 128 + bn);
        __syncthreads();
#pragma unroll
        for (int k = 0; k < 8; k++) {
            float a[8], b[8];
            *(float4*)(a)     = *(const float4*)&As[k][ty * 4];
            *(float4*)(a + 4) = *(const float4*)&As[k][64 + ty * 4];
            *(float4*)(b)     = *(const float4*)&Bs[k][tx * 4];
            *(float4*)(b + 4) = *(const float4*)&Bs[k][64 + tx * 4];
#pragma unroll
            for (int i = 0; i < 8; i++)
#pragma unroll
                for (int j = 0; j < 8; j++) acc[i][j] += a[i] * b[j];
        }
        __syncthreads();
    }
    float* U = (float*)g_u;
#pragma unroll
    for (int i = 0; i < 8; i++) {
        int r = (i < 4) ? (row0 + ty * 4 + i) : (row0 + 64 + ty * 4 + (i - 4));
        if (r < n) {
            float d = g_dis[r];
            float4 v0 = make_float4(acc[i][0] * d, acc[i][1] * d, acc[i][2] * d, acc[i][3] * d);
            float4 v1 = make_float4(acc[i][4] * d, acc[i][5] * d, acc[i][6] * d, acc[i][7] * d);
            *(float4*)(U + (size_t)r * 128 + tx * 4) = v0;
            *(float4*)(U + (size_t)r * 128 + 64 + tx * 4) = v1;
        }
    }
}

// ---------------- fused CSR aggregation + finalize (128-dim) -------------
// warp per node; lane owns one float4 column slice. h = relu(dis*(sum+u)+b)
__global__ void k_agg128(const float* __restrict__ bias, int n) {
    int gid = blockIdx.x * blockDim.x + threadIdx.x;
    int i = gid >> 5;
    int lane = threadIdx.x & 31;
    if (i >= n) return;
    int start = g_rowstart[i];
    int cnt   = g_deg[i] - 1;
    float4 acc0 = g_u[(size_t)i * 32 + lane];   // self-loop contribution
    float4 acc1 = make_float4(0.f, 0.f, 0.f, 0.f);
    int j = 0;
    for (; j + 4 <= cnt; j += 4) {
        int s0 = g_col[start + j + 0];
        int s1 = g_col[start + j + 1];
        int s2 = g_col[start + j + 2];
        int s3 = g_col[start + j + 3];
        float4 v0 = g_u[(size_t)s0 * 32 + lane];
        float4 v1 = g_u[(size_t)s1 * 32 + lane];
        float4 v2 = g_u[(size_t)s2 * 32 + lane];
        float4 v3 = g_u[(size_t)s3 * 32 + lane];
        acc0.x += v0.x; acc0.y += v0.y; acc0.z += v0.z; acc0.w += v0.w;
        acc1.x += v1.x; acc1.y += v1.y; acc1.z += v1.z; acc1.w += v1.w;
        acc0.x += v2.x; acc0.y += v2.y; acc0.z += v2.z; acc0.w += v2.w;
        acc1.x += v3.x; acc1.y += v3.y; acc1.z += v3.z; acc1.w += v3.w;
    }
    for (; j < cnt; j++) {
        int s = g_col[start + j];
        float4 v = g_u[(size_t)s * 32 + lane];
        acc0.x += v.x; acc0.y += v.y; acc0.z += v.z; acc0.w += v.w;
    }
    float d = g_dis[i];
    float4 b = *(const float4*)(bias + lane * 4);
    float4 o;
    o.x = fmaxf(d * (acc0.x + acc1.x) + b.x, 0.f);
    o.y = fmaxf(d * (acc0.y + acc1.y) + b.y, 0.f);
    o.z = fmaxf(d * (acc0.z + acc1.z) + b.z, 0.f);
    o.w = fmaxf(d * (acc0.w + acc1.w) + b.w, 0.f);
    g_h[(size_t)i * 32 + lane] = o;
}

// ---------------- fused pool (mean over sorted batch) + output dense -----
__global__ void k_pool_out(const int* __restrict__ batch, int n,
                           const float* __restrict__ W,
                           const float* __restrict__ b,
                           float* __restrict__ out) {
    __shared__ float pooled[128];
    __shared__ int seg[2];
    int g = blockIdx.x;
    int j = threadIdx.x;
    if (j < 2) {
        int v = g + j;                 // lower_bound(batch, v)
        int lo = 0, hi = n;
        while (lo < hi) {
            int m = (lo + hi) >> 1;
            if (batch[m] < v) lo = m + 1; else hi = m;
        }
        seg[j] = lo;
    }
    __syncthreads();
    int s = seg[0], e = seg[1];
    const float* H = (const float*)g_h;
    float sum = 0.f;
    for (int i = s; i < e; i++) sum += H[(size_t)i * 128 + j];
    float inv = 1.f / fmaxf((float)(e - s), 1.f);
    pooled[j] = sum * inv;
    __syncthreads();
    float acc = b[j];
#pragma unroll 8
    for (int k = 0; k < 128; k++) acc += pooled[k] * W[k * 128 + j];
    out[g * 128 + j] = acc;
}

// ---------------- launch -------------------------------------------------
extern "C" void kernel_launch(void* const* d_in, const int* in_sizes, int n_in,
                              void* d_out, int out_size) {
    const float* x     = (const float*)d_in[0];
    const int*   ei    = (const int*)d_in[1];    // int32 (JAX x64 disabled)
    const int*   batch = (const int*)d_in[2];
    const float* W_d1 = (const float*)d_in[3];
    const float* b_d1 = (const float*)d_in[4];
    const float* W_g1 = (const float*)d_in[5];
    const float* b_g1 = (const float*)d_in[6];
    const float* W_g2 = (const float*)d_in[7];
    const float* b_g2 = (const float*)d_in[8];
    const float* W_g3 = (const float*)d_in[9];
    const float* b_g3 = (const float*)d_in[10];
    const float* W_d2 = (const float*)d_in[11];
    const float* b_d2 = (const float*)d_in[12];
    float* out = (float*)d_out;

    const int N = in_sizes[0] / 4;   // 100000
    const int E = in_sizes[1] / 2;   // 1600000
    const int* src = ei;
    const int* dst = ei + E;
    const int T = 256;
    const int NB = (N + 255) / 256;  // 391

    // structure: degree, norm, CSR (by dst)
    k_init<<<(N + T - 1) / T, T>>>(N);
    k_deg<<<(E + T - 1) / T, T>>>(dst, E);
    k_dis<<<(N + T - 1) / T, T>>>(N);
    k_scan1<<<NB, 256>>>(N);
    k_scan2<<<1, 512>>>(NB);
    k_scan3<<<NB, 256>>>(N);
    k_fill<<<(E + T - 1) / T, T>>>(src, dst, E);

    // layer 1: aggregate 4-dim, then fused 4->128 projection
    k_dense1<<<(N + T - 1) / T, T>>>(x, W_d1, b_d1, N);
    k_layer1<<<(N * 32 + T - 1) / T, T>>>(W_g1, b_g1, N);

    const int gemm_blocks = (N + 127) / 128;
    const int agg_blocks  = (int)(((long long)N * 32 + T - 1) / T);

    // layer 2
    k_gemm_scale<<<gemm_blocks, T>>>(W_g2, N);
    k_agg128<<<agg_blocks, T>>>(b_g2, N);

    // layer 3
    k_gemm_scale<<<gemm_blocks, T>>>(W_g3, N);
    k_agg128<<<agg_blocks, T>>>(b_g3, N);

    // fused pooling + output head
    k_pool_out<<<NG, 128>>>(batch, N, W_d2, b_d2, out);
}